// round 1
// baseline (speedup 1.0000x reference)
#include <cuda_runtime.h>
#include <cstdint>

// GeGate: out = capped_relu(x * w[col] + b[col])
//   x: [B=8192, D=4096] fp32, w/b: [D] fp32, out: [B, D] fp32
// Pure HBM-bound streaming kernel: 128 MiB in + 128 MiB out.
// float4 vectorized, D power-of-two -> column via mask, w/b stay L2-resident.

#define D_LOG2 12
#define D_MASK 4095  // D - 1

__global__ void __launch_bounds__(256)
gegate_kernel(const float4* __restrict__ x,
              const float4* __restrict__ w,
              const float4* __restrict__ b,
              float4* __restrict__ out,
              int n_vec)  // number of float4 elements
{
    int i = blockIdx.x * blockDim.x + threadIdx.x;
    int stride = gridDim.x * blockDim.x;

    for (; i < n_vec; i += stride) {
        // column (in floats) of this float4 = (i*4) & (D-1); as float4 index:
        int dvec = i & (D_MASK >> 2);  // i % (D/4)

        float4 xv = x[i];
        float4 wv = __ldg(&w[dvec]);
        float4 bv = __ldg(&b[dvec]);

        float4 y;
        y.x = fmaf(xv.x, wv.x, bv.x);
        y.y = fmaf(xv.y, wv.y, bv.y);
        y.z = fmaf(xv.z, wv.z, bv.z);
        y.w = fmaf(xv.w, wv.w, bv.w);

        // CappedReLU: keep y where 0 < y <= 1, else 0. Branch-free select.
        y.x = (y.x > 0.0f && y.x <= 1.0f) ? y.x : 0.0f;
        y.y = (y.y > 0.0f && y.y <= 1.0f) ? y.y : 0.0f;
        y.z = (y.z > 0.0f && y.z <= 1.0f) ? y.z : 0.0f;
        y.w = (y.w > 0.0f && y.w <= 1.0f) ? y.w : 0.0f;

        out[i] = y;
    }
}

extern "C" void kernel_launch(void* const* d_in, const int* in_sizes, int n_in,
                              void* d_out, int out_size)
{
    const float4* x = (const float4*)d_in[0];
    const float4* w = (const float4*)d_in[1];
    const float4* b = (const float4*)d_in[2];
    float4* out = (float4*)d_out;

    int n = in_sizes[0];          // 8192*4096 = 33554432 floats
    int n_vec = n >> 2;           // 8388608 float4s

    const int threads = 256;
    int blocks = (n_vec + threads - 1) / threads;  // 32768 — exact, no tail

    gegate_kernel<<<blocks, threads>>>(x, w, b, out, n_vec);
}

// round 2
// speedup vs baseline: 1.0348x; 1.0348x over previous
#include <cuda_runtime.h>
#include <cstdint>

// GeGate: out = capped_relu(x * w[col] + b[col])
//   x: [B=8192, D=4096] fp32, w/b: [D] fp32, out: [B, D] fp32
// HBM-bound streaming kernel. Each thread handles 4 float4s in the SAME
// column across 4 consecutive rows:
//   - 4 front-batched LDG.128 (MLP_p1=4) to saturate DRAM
//   - w/b loaded once per thread (L1-resident, 16KB each)
//   - __ldcs/__stcs: evict-first for the touch-once x/out streams

#define DVEC 1024          // D/4 float4 columns
#define DVEC_MASK 1023
#define ROWS_PER_THREAD 4

__global__ void __launch_bounds__(256)
gegate_kernel(const float4* __restrict__ x,
              const float4* __restrict__ w,
              const float4* __restrict__ b,
              float4* __restrict__ out,
              int n_vec)
{
    int t = blockIdx.x * blockDim.x + threadIdx.x;
    int col = t & DVEC_MASK;          // float4 column index
    int row0 = (t >> 10) << 2;        // first of 4 rows for this thread
    long base = (long)row0 * DVEC + col;

    if (base + 3L * DVEC < (long)n_vec) {
        // Front-batch 4 independent 128-bit loads (MLP_p1 = 4)
        float4 x0 = __ldcs(&x[base + 0L * DVEC]);
        float4 x1 = __ldcs(&x[base + 1L * DVEC]);
        float4 x2 = __ldcs(&x[base + 2L * DVEC]);
        float4 x3 = __ldcs(&x[base + 3L * DVEC]);

        float4 wv = __ldg(&w[col]);
        float4 bv = __ldg(&b[col]);

        float4 y0, y1, y2, y3;
        y0.x = fmaf(x0.x, wv.x, bv.x); y0.y = fmaf(x0.y, wv.y, bv.y);
        y0.z = fmaf(x0.z, wv.z, bv.z); y0.w = fmaf(x0.w, wv.w, bv.w);
        y1.x = fmaf(x1.x, wv.x, bv.x); y1.y = fmaf(x1.y, wv.y, bv.y);
        y1.z = fmaf(x1.z, wv.z, bv.z); y1.w = fmaf(x1.w, wv.w, bv.w);
        y2.x = fmaf(x2.x, wv.x, bv.x); y2.y = fmaf(x2.y, wv.y, bv.y);
        y2.z = fmaf(x2.z, wv.z, bv.z); y2.w = fmaf(x2.w, wv.w, bv.w);
        y3.x = fmaf(x3.x, wv.x, bv.x); y3.y = fmaf(x3.y, wv.y, bv.y);
        y3.z = fmaf(x3.z, wv.z, bv.z); y3.w = fmaf(x3.w, wv.w, bv.w);

        y0.x = (y0.x > 0.0f && y0.x <= 1.0f) ? y0.x : 0.0f;
        y0.y = (y0.y > 0.0f && y0.y <= 1.0f) ? y0.y : 0.0f;
        y0.z = (y0.z > 0.0f && y0.z <= 1.0f) ? y0.z : 0.0f;
        y0.w = (y0.w > 0.0f && y0.w <= 1.0f) ? y0.w : 0.0f;
        y1.x = (y1.x > 0.0f && y1.x <= 1.0f) ? y1.x : 0.0f;
        y1.y = (y1.y > 0.0f && y1.y <= 1.0f) ? y1.y : 0.0f;
        y1.z = (y1.z > 0.0f && y1.z <= 1.0f) ? y1.z : 0.0f;
        y1.w = (y1.w > 0.0f && y1.w <= 1.0f) ? y1.w : 0.0f;
        y2.x = (y2.x > 0.0f && y2.x <= 1.0f) ? y2.x : 0.0f;
        y2.y = (y2.y > 0.0f && y2.y <= 1.0f) ? y2.y : 0.0f;
        y2.z = (y2.z > 0.0f && y2.z <= 1.0f) ? y2.z : 0.0f;
        y2.w = (y2.w > 0.0f && y2.w <= 1.0f) ? y2.w : 0.0f;
        y3.x = (y3.x > 0.0f && y3.x <= 1.0f) ? y3.x : 0.0f;
        y3.y = (y3.y > 0.0f && y3.y <= 1.0f) ? y3.y : 0.0f;
        y3.z = (y3.z > 0.0f && y3.z <= 1.0f) ? y3.z : 0.0f;
        y3.w = (y3.w > 0.0f && y3.w <= 1.0f) ? y3.w : 0.0f;

        __stcs(&out[base + 0L * DVEC], y0);
        __stcs(&out[base + 1L * DVEC], y1);
        __stcs(&out[base + 2L * DVEC], y2);
        __stcs(&out[base + 3L * DVEC], y3);
    } else {
        // Tail path (never taken for 8192x4096, kept for safety)
        for (int r = 0; r < ROWS_PER_THREAD; r++) {
            long idx = base + (long)r * DVEC;
            if (idx < (long)n_vec) {
                float4 xv = __ldcs(&x[idx]);
                float4 wv = __ldg(&w[col]);
                float4 bv = __ldg(&b[col]);
                float4 y;
                y.x = fmaf(xv.x, wv.x, bv.x);
                y.y = fmaf(xv.y, wv.y, bv.y);
                y.z = fmaf(xv.z, wv.z, bv.z);
                y.w = fmaf(xv.w, wv.w, bv.w);
                y.x = (y.x > 0.0f && y.x <= 1.0f) ? y.x : 0.0f;
                y.y = (y.y > 0.0f && y.y <= 1.0f) ? y.y : 0.0f;
                y.z = (y.z > 0.0f && y.z <= 1.0f) ? y.z : 0.0f;
                y.w = (y.w > 0.0f && y.w <= 1.0f) ? y.w : 0.0f;
                __stcs(&out[idx], y);
            }
        }
    }
}

extern "C" void kernel_launch(void* const* d_in, const int* in_sizes, int n_in,
                              void* d_out, int out_size)
{
    const float4* x = (const float4*)d_in[0];
    const float4* w = (const float4*)d_in[1];
    const float4* b = (const float4*)d_in[2];
    float4* out = (float4*)d_out;

    int n = in_sizes[0];                 // 33554432 floats
    int n_vec = n >> 2;                  // 8388608 float4s

    const int threads = 256;
    int total_threads = n_vec / ROWS_PER_THREAD;      // 2097152
    int blocks = (total_threads + threads - 1) / threads;  // 8192

    gegate_kernel<<<blocks, threads>>>(x, w, b, out, n_vec);
}